// round 2
// baseline (speedup 1.0000x reference)
#include <cuda_runtime.h>
#include <cstdint>

#define Bsz 256
#define Ssz 256
#define Esz 256
#define Hsz 1024
#define G4  4096   // 4*H

#define BM  64     // batch rows per block
#define BHt 32     // hidden cols per gate per block (4 gates -> 128 virtual cols)
#define KT  16     // k tile
#define AS_STRIDE 68
#define BS_STRIDE 132

// Scratch: projection lookup tables (device globals — no allocation allowed)
__device__ float g_letter_proj[30 * G4];
__device__ float g_state_proj[4 * G4];

// ---------------------------------------------------------------------------
// packed f32x2 helpers (FFMA2: 2 fp32 FMA lanes per instruction)
// ---------------------------------------------------------------------------
__device__ __forceinline__ unsigned long long pk2(float lo, float hi) {
    unsigned long long r;
    asm("mov.b64 %0, {%1,%2};" : "=l"(r) : "f"(lo), "f"(hi));
    return r;
}
__device__ __forceinline__ void fma2(unsigned long long& d,
                                     unsigned long long a,
                                     unsigned long long b) {
    asm("fma.rn.f32x2 %0, %1, %2, %0;" : "+l"(d) : "l"(a), "l"(b));
}
__device__ __forceinline__ float2 unpk2(unsigned long long v) {
    float lo, hi;
    asm("mov.b64 {%0,%1}, %2;" : "=f"(lo), "=f"(hi) : "l"(v));
    return make_float2(lo, hi);
}

__device__ __forceinline__ float sigmoidf_(float x) {
    return 1.0f / (1.0f + expf(-x));
}

// ---------------------------------------------------------------------------
// Projection kernel: letter_proj[30][4096] (incl. biases) and state_proj[4][4096]
// grid (512, 34), 256 threads (8 warps). Each warp -> one (token, g) dot product.
// ---------------------------------------------------------------------------
__global__ void proj_kernel(const float* __restrict__ letter_emb,
                            const float* __restrict__ state_emb,
                            const float* __restrict__ W_ih,
                            const float* __restrict__ b_ih,
                            const float* __restrict__ b_hh) {
    int tok  = blockIdx.y;                       // 0..33
    int g    = blockIdx.x * 8 + (threadIdx.x >> 5);   // 0..4095
    int lane = threadIdx.x & 31;

    const float* emb;
    const float* w;
    if (tok < 30) {
        emb = letter_emb + tok * Esz;
        w   = W_ih + (size_t)g * (2 * Esz);          // letter half: cols [0, E)
    } else {
        emb = state_emb + (tok - 30) * Esz;
        w   = W_ih + (size_t)g * (2 * Esz) + Esz;    // state half: cols [E, 2E)
    }

    float acc = 0.f;
    for (int k = lane; k < Esz; k += 32)
        acc += emb[k] * w[k];
    #pragma unroll
    for (int off = 16; off; off >>= 1)
        acc += __shfl_xor_sync(0xFFFFFFFFu, acc, off);

    if (lane == 0) {
        if (tok < 30)
            g_letter_proj[tok * G4 + g] = acc + b_ih[g] + b_hh[g];
        else
            g_state_proj[(tok - 30) * G4 + g] = acc;
    }
}

// ---------------------------------------------------------------------------
// Fused LSTM step: gates = x_proj(lookup) + h_{s-1} @ W_hh^T ; nonlinearities ;
// write h_s, c_s directly into d_out. h_{s-1}, c_{s-1} read from d_out.
// grid (H/BHt=32, B/BM=4) = 128 blocks, 256 threads.
// ---------------------------------------------------------------------------
__global__ void __launch_bounds__(256)
lstm_step(const int* __restrict__ letter_seq,
          const int* __restrict__ state_seq,
          const float* __restrict__ W_hh,
          float* __restrict__ out_h,
          float* __restrict__ out_c,
          int s) {
    __shared__ float As[KT][AS_STRIDE];   // [k][row]   h_prev tile (transposed)
    __shared__ float Bs[KT][BS_STRIDE];   // [k][col]   W_hh tile (col = gate*32 + h)

    const int tid = threadIdx.x;
    const int tx  = tid & 15;             // 0..15 -> h pair index
    const int ty  = tid >> 4;             // 0..15 -> row group (4 rows each)
    const int h0  = blockIdx.x * BHt;
    const int bm0 = blockIdx.y * BM;

    // accumulators: 4 rows x 4 gates, each f32x2 = (h0+tx*2, h0+tx*2+1)
    unsigned long long acc[4][4];
    #pragma unroll
    for (int r = 0; r < 4; r++)
        #pragma unroll
        for (int g = 0; g < 4; g++)
            acc[r][g] = 0ULL;

    if (s > 0) {
        const int a_m  = tid >> 2;        // 0..63 row
        const int a_kq = tid & 3;         // 0..3  k quad

        for (int k0 = 0; k0 < Hsz; k0 += KT) {
            // --- load A tile: h_prev[bm0+a_m][k0 + a_kq*4 .. +3] ---
            const float* ap = out_h + (size_t)(bm0 + a_m) * (Ssz * Hsz)
                                    + (size_t)(s - 1) * Hsz + k0 + a_kq * 4;
            float4 a4 = *(const float4*)ap;
            As[a_kq * 4 + 0][a_m] = a4.x;
            As[a_kq * 4 + 1][a_m] = a4.y;
            As[a_kq * 4 + 2][a_m] = a4.z;
            As[a_kq * 4 + 3][a_m] = a4.w;

            // --- load B tile: W_hh[gate*H + h0 + (col&31)][k0 + kq*4 .. +3] ---
            #pragma unroll
            for (int i = 0; i < 2; i++) {
                int idx = tid + i * 256;
                int col = idx >> 2;       // 0..127
                int kq  = idx & 3;
                int grow = (col >> 5) * Hsz + h0 + (col & 31);
                const float* bp = W_hh + (size_t)grow * Hsz + k0 + kq * 4;
                float4 b4 = *(const float4*)bp;
                Bs[kq * 4 + 0][col] = b4.x;
                Bs[kq * 4 + 1][col] = b4.y;
                Bs[kq * 4 + 2][col] = b4.z;
                Bs[kq * 4 + 3][col] = b4.w;
            }
            __syncthreads();

            #pragma unroll
            for (int k = 0; k < KT; k++) {
                float4 a4 = *(const float4*)&As[k][ty * 4];
                unsigned long long ap2[4];
                ap2[0] = pk2(a4.x, a4.x);
                ap2[1] = pk2(a4.y, a4.y);
                ap2[2] = pk2(a4.z, a4.z);
                ap2[3] = pk2(a4.w, a4.w);
                #pragma unroll
                for (int g = 0; g < 4; g++) {
                    unsigned long long b2 =
                        *(const unsigned long long*)&Bs[k][g * 32 + tx * 2];
                    #pragma unroll
                    for (int r = 0; r < 4; r++)
                        fma2(acc[r][g], ap2[r], b2);
                }
            }
            __syncthreads();
        }
    }

    // --- epilogue: add x_proj lookup, gate nonlinearities, write h,c ---
    const int h_base = h0 + tx * 2;
    #pragma unroll
    for (int r = 0; r < 4; r++) {
        const int b  = bm0 + ty * 4 + r;
        const int l  = letter_seq[b * Ssz + s];
        const int st = state_seq[b * Ssz + s];
        const float* lp = g_letter_proj + (size_t)l  * G4;
        const float* sp = g_state_proj  + (size_t)st * G4;

        float2 pre[4];
        #pragma unroll
        for (int g = 0; g < 4; g++) {
            float2 a = unpk2(acc[r][g]);
            int gg = g * Hsz + h_base;
            pre[g].x = a.x + lp[gg]     + sp[gg];
            pre[g].y = a.y + lp[gg + 1] + sp[gg + 1];
        }

        const size_t base = (size_t)b * (Ssz * Hsz) + (size_t)s * Hsz + h_base;

        float2 cprev = make_float2(0.f, 0.f);
        if (s > 0)
            cprev = *(const float2*)(out_c + base - Hsz);

        float i0 = sigmoidf_(pre[0].x), i1 = sigmoidf_(pre[0].y);
        float f0 = sigmoidf_(pre[1].x), f1 = sigmoidf_(pre[1].y);
        float g0 = tanhf(pre[2].x),     g1 = tanhf(pre[2].y);
        float o0 = sigmoidf_(pre[3].x), o1 = sigmoidf_(pre[3].y);

        float c0 = f0 * cprev.x + i0 * g0;
        float c1 = f1 * cprev.y + i1 * g1;
        float h0v = o0 * tanhf(c0);
        float h1v = o1 * tanhf(c1);

        *(float2*)(out_h + base) = make_float2(h0v, h1v);
        *(float2*)(out_c + base) = make_float2(c0, c1);
    }
}

// ---------------------------------------------------------------------------
// Launch: proj tables once, then 256 sequential fused steps (all graph-capturable)
// ---------------------------------------------------------------------------
extern "C" void kernel_launch(void* const* d_in, const int* in_sizes, int n_in,
                              void* d_out, int out_size) {
    const int*   letter_seq = (const int*)d_in[0];
    const int*   state_seq  = (const int*)d_in[1];
    const float* letter_emb = (const float*)d_in[2];
    const float* state_emb  = (const float*)d_in[3];
    const float* W_ih       = (const float*)d_in[4];
    const float* W_hh       = (const float*)d_in[5];
    const float* b_ih       = (const float*)d_in[6];
    const float* b_hh       = (const float*)d_in[7];

    float* out_h = (float*)d_out;
    float* out_c = out_h + (size_t)Bsz * Ssz * Hsz;

    // FIX (R1 bug): one warp per gate element -> need G4/8 = 512 blocks in x,
    // not 16. Previously only gates [0,128) were computed; the rest read as 0.
    proj_kernel<<<dim3(G4 / 8, 34), 256>>>(letter_emb, state_emb,
                                           W_ih, b_ih, b_hh);

    for (int s = 0; s < Ssz; s++) {
        lstm_step<<<dim3(Hsz / BHt, Bsz / BM), 256>>>(
            letter_seq, state_seq, W_hh, out_h, out_c, s);
    }
}

// round 4
// speedup vs baseline: 3.3431x; 3.3431x over previous
#include <cuda_runtime.h>
#include <cuda_bf16.h>
#include <cstdint>

#define Bsz 256
#define Ssz 256
#define Esz 256
#define Hsz 1024
#define G4  4096   // 4*H

// ---- step kernel tiling ----
#define BMt 64                  // M tile (batch rows per CTA)
#define HT  32                  // h columns per gate per CTA
#define NT  128                 // N tile = 4 gates * HT
#define KC  64                  // K chunk (bf16 elements = 128 B row)
#define NCHUNK (Hsz / KC)       // 16

// ---- smem layout ----
#define A_MAT_BYTES (BMt * KC * 2)                     // 8 KB per matrix
#define B_MAT_BYTES (NT * KC * 2)                      // 16 KB per matrix
#define STAGE_BYTES (2 * A_MAT_BYTES + 2 * B_MAT_BYTES) // 48 KB
#define OFF_AHI 0
#define OFF_ALO (A_MAT_BYTES)
#define OFF_BHI (2 * A_MAT_BYTES)
#define OFF_BLO (2 * A_MAT_BYTES + B_MAT_BYTES)
#define SMEM_TOTAL (2 * STAGE_BYTES)                   // 96 KB
#define DPITCH 132

// ---- device globals (no allocation allowed) ----
__device__ float g_letter_proj[30 * G4];
__device__ float g_state_proj[4 * G4];
__device__ __nv_bfloat16 g_W_hi[(size_t)G4 * Hsz];   // 8 MB
__device__ __nv_bfloat16 g_W_lo[(size_t)G4 * Hsz];   // 8 MB
__device__ __nv_bfloat16 g_h_hi[2][Bsz * Hsz];
__device__ __nv_bfloat16 g_h_lo[2][Bsz * Hsz];

// ---------------------------------------------------------------------------
// PTX helpers (sm_80-era instructions only — no arch-suffix features)
// ---------------------------------------------------------------------------
__device__ __forceinline__ uint32_t smem_u32(const void* p) {
    uint32_t a;
    asm("{ .reg .u64 t; cvta.to.shared.u64 t, %1; cvt.u32.u64 %0, t; }"
        : "=r"(a) : "l"(p));
    return a;
}
__device__ __forceinline__ void cp16(uint32_t s, const void* g) {
    asm volatile("cp.async.cg.shared.global [%0], [%1], 16;"
                 :: "r"(s), "l"(g) : "memory");
}
#define CP_COMMIT() asm volatile("cp.async.commit_group;" ::: "memory")
#define CP_WAIT1()  asm volatile("cp.async.wait_group 1;" ::: "memory")

__device__ __forceinline__ void ldsm4(uint32_t a, uint32_t* r) {
    asm volatile("ldmatrix.sync.aligned.m8n8.x4.shared.b16 {%0,%1,%2,%3}, [%4];"
                 : "=r"(r[0]), "=r"(r[1]), "=r"(r[2]), "=r"(r[3]) : "r"(a));
}
__device__ __forceinline__ void mma16816(float* c, const uint32_t* a,
                                         const uint32_t* b) {
    asm volatile(
        "mma.sync.aligned.m16n8k16.row.col.f32.bf16.bf16.f32 "
        "{%0,%1,%2,%3}, {%4,%5,%6,%7}, {%8,%9}, {%0,%1,%2,%3};"
        : "+f"(c[0]), "+f"(c[1]), "+f"(c[2]), "+f"(c[3])
        : "r"(a[0]), "r"(a[1]), "r"(a[2]), "r"(a[3]), "r"(b[0]), "r"(b[1]));
}
__device__ __forceinline__ float sigmoidf_(float x) {
    return 1.0f / (1.0f + expf(-x));
}

// ---------------------------------------------------------------------------
// One-time prep: split W_hh into bf16 hi/lo
// ---------------------------------------------------------------------------
__global__ void wsplit_kernel(const float* __restrict__ W) {
    size_t i = ((size_t)blockIdx.x * blockDim.x + threadIdx.x) * 4;
    float4 w = *(const float4*)(W + i);
    float v[4] = {w.x, w.y, w.z, w.w};
    #pragma unroll
    for (int j = 0; j < 4; j++) {
        __nv_bfloat16 hi = __float2bfloat16(v[j]);
        g_W_hi[i + j] = hi;
        g_W_lo[i + j] = __float2bfloat16(v[j] - __bfloat162float(hi));
    }
}

// ---------------------------------------------------------------------------
// One-time prep: x_proj lookup tables (incl. biases)
// ---------------------------------------------------------------------------
__global__ void proj_kernel(const float* __restrict__ letter_emb,
                            const float* __restrict__ state_emb,
                            const float* __restrict__ W_ih,
                            const float* __restrict__ b_ih,
                            const float* __restrict__ b_hh) {
    int tok  = blockIdx.y;
    int g    = blockIdx.x * 8 + (threadIdx.x >> 5);
    int lane = threadIdx.x & 31;

    const float* emb;
    const float* w;
    if (tok < 30) {
        emb = letter_emb + tok * Esz;
        w   = W_ih + (size_t)g * (2 * Esz);
    } else {
        emb = state_emb + (tok - 30) * Esz;
        w   = W_ih + (size_t)g * (2 * Esz) + Esz;
    }

    float acc = 0.f;
    for (int k = lane; k < Esz; k += 32)
        acc += emb[k] * w[k];
    #pragma unroll
    for (int off = 16; off; off >>= 1)
        acc += __shfl_xor_sync(0xFFFFFFFFu, acc, off);

    if (lane == 0) {
        if (tok < 30)
            g_letter_proj[tok * G4 + g] = acc + b_ih[g] + b_hh[g];
        else
            g_state_proj[(tok - 30) * G4 + g] = acc;
    }
}

// ---------------------------------------------------------------------------
// HMMA LSTM step. grid (Hsz/HT=32, Bsz/BMt=4) = 128 CTAs, 256 threads (8 warps).
// D[m][n] = sum_k h_prev[bm0+m][k] * W_hh[(n>>5)*H + h0 + (n&31)][k]
// split: D = Ahi*Bhi + Alo*Bhi + Ahi*Blo  (fp32 accum)
// ---------------------------------------------------------------------------
__global__ void __launch_bounds__(256, 1)
lstm_step_mma(const int* __restrict__ letter_seq,
              const int* __restrict__ state_seq,
              float* __restrict__ out_h,
              float* __restrict__ out_c,
              int s) {
    extern __shared__ char smem[];
    const uint32_t smem_base = smem_u32(smem);

    const int tid = threadIdx.x;
    const int h0  = blockIdx.x * HT;
    const int bm0 = blockIdx.y * BMt;
    const int rbuf = (s & 1) ^ 1;
    const int wbuf = s & 1;

    const int wid = tid >> 5;
    const int l   = tid & 31;
    const int wm  = wid >> 2;         // 0..1
    const int wn  = wid & 3;          // 0..3

    float acc[2][4][4];
    #pragma unroll
    for (int i = 0; i < 2; i++)
        #pragma unroll
        for (int j = 0; j < 4; j++)
            #pragma unroll
            for (int k = 0; k < 4; k++)
                acc[i][j][k] = 0.f;

    if (s > 0) {
        // ---- stage-load lambda state (per-thread constants) ----
        const int r  = tid >> 3;                 // 0..31
        const int gq = tid & 7;                  // granule within 128B row
        const uint32_t sw = (uint32_t)((gq ^ (r & 7)) * 16);
        const __nv_bfloat16* hh = g_h_hi[rbuf] + (size_t)(bm0 + r) * Hsz + gq * 8;
        const __nv_bfloat16* hl = g_h_lo[rbuf] + (size_t)(bm0 + r) * Hsz + gq * 8;
        const size_t wrow = (size_t)(h0 + r) * Hsz + gq * 8;

        auto load_stage = [&](int ch) {
            const int k0 = ch * KC;
            const uint32_t sb = smem_base + (uint32_t)(ch & 1) * STAGE_BYTES;
            // A rows r and r+32 (hi + lo)
            cp16(sb + OFF_AHI + r * 128 + sw,        hh + k0);
            cp16(sb + OFF_AHI + (r + 32) * 128 + sw, hh + k0 + 32 * Hsz);
            cp16(sb + OFF_ALO + r * 128 + sw,        hl + k0);
            cp16(sb + OFF_ALO + (r + 32) * 128 + sw, hl + k0 + 32 * Hsz);
            // B rows: n = gate*32 + r, gate 0..3 (hi + lo)
            #pragma unroll
            for (int gate = 0; gate < 4; gate++) {
                const size_t off = wrow + (size_t)gate * Hsz * Hsz + k0;
                const uint32_t sn = (uint32_t)(gate * 32 + r) * 128 + sw;
                cp16(sb + OFF_BHI + sn, g_W_hi + off);
                cp16(sb + OFF_BLO + sn, g_W_lo + off);
            }
        };

        // ---- ldmatrix lane constants ----
        const int a_r0 = wm * 32 + (l & 7) + ((l >> 3) & 1) * 8;  // +16 for mf=1
        const int a_kh = l >> 4;
        const int a_swr = a_r0 & 7;
        const int b_n0 = wn * 32 + (l & 7) + (l >> 4) * 8;        // +16 for x=1
        const int b_kh = (l >> 3) & 1;
        const int b_swr = b_n0 & 7;

        load_stage(0); CP_COMMIT();
        load_stage(1); CP_COMMIT();

        for (int ch = 0; ch < NCHUNK; ch++) {
            CP_WAIT1();
            __syncthreads();

            const uint32_t sb = smem_base + (uint32_t)(ch & 1) * STAGE_BYTES;
            #pragma unroll
            for (int ks = 0; ks < 4; ks++) {
                const int agq = ks * 2 + a_kh;
                const int bgq = ks * 2 + b_kh;
                uint32_t ah[2][4], al[2][4], bh[2][4], bl[2][4];
                #pragma unroll
                for (int mf = 0; mf < 2; mf++) {
                    uint32_t arow = (uint32_t)(a_r0 + mf * 16) * 128
                                  + (uint32_t)((agq ^ a_swr) * 16);
                    ldsm4(sb + OFF_AHI + arow, ah[mf]);
                    ldsm4(sb + OFF_ALO + arow, al[mf]);
                }
                #pragma unroll
                for (int x = 0; x < 2; x++) {
                    uint32_t brow = (uint32_t)(b_n0 + x * 16) * 128
                                  + (uint32_t)((bgq ^ b_swr) * 16);
                    ldsm4(sb + OFF_BHI + brow, bh[x]);
                    ldsm4(sb + OFF_BLO + brow, bl[x]);
                }
                #pragma unroll
                for (int mf = 0; mf < 2; mf++)
                    #pragma unroll
                    for (int x = 0; x < 2; x++) {
                        mma16816(acc[mf][x * 2],     ah[mf], &bh[x][0]);
                        mma16816(acc[mf][x * 2 + 1], ah[mf], &bh[x][2]);
                        mma16816(acc[mf][x * 2],     al[mf], &bh[x][0]);
                        mma16816(acc[mf][x * 2 + 1], al[mf], &bh[x][2]);
                        mma16816(acc[mf][x * 2],     ah[mf], &bl[x][0]);
                        mma16816(acc[mf][x * 2 + 1], ah[mf], &bl[x][2]);
                    }
            }
            __syncthreads();
            if (ch + 2 < NCHUNK) load_stage(ch + 2);
            CP_COMMIT();
        }

        // ---- dump accums to smem D[64][DPITCH] ----
        float* Dsm = (float*)smem;
        #pragma unroll
        for (int mf = 0; mf < 2; mf++)
            #pragma unroll
            for (int nf = 0; nf < 4; nf++) {
                int m = wm * 32 + mf * 16 + (l >> 2);
                int n = wn * 32 + nf * 8 + (l & 3) * 2;
                *(float2*)&Dsm[m * DPITCH + n] =
                    make_float2(acc[mf][nf][0], acc[mf][nf][1]);
                *(float2*)&Dsm[(m + 8) * DPITCH + n] =
                    make_float2(acc[mf][nf][2], acc[mf][nf][3]);
            }
        __syncthreads();
    }

    // ---- fused LSTM cell epilogue ----
    {
        const float* Dsm = (const float*)smem;
        const int m  = tid >> 2;          // 0..63
        const int hq = tid & 3;           // 8-col group
        const int b  = bm0 + m;
        const int lt = letter_seq[b * Ssz + s];
        const int st = state_seq[b * Ssz + s];
        const float* lp = g_letter_proj + (size_t)lt * G4 + h0;
        const float* sp = g_state_proj  + (size_t)st * G4 + h0;
        const size_t base = (size_t)b * (Ssz * Hsz) + (size_t)s * Hsz + h0;
        const int hl0 = hq * 8;

        float hv[8], cv[8];
        #pragma unroll
        for (int j = 0; j < 8; j++) {
            const int hlc = hl0 + j;
            float pi, pf, pg, po;
            if (s > 0) {
                pi = Dsm[m * DPITCH + 0 * 32 + hlc];
                pf = Dsm[m * DPITCH + 1 * 32 + hlc];
                pg = Dsm[m * DPITCH + 2 * 32 + hlc];
                po = Dsm[m * DPITCH + 3 * 32 + hlc];
            } else {
                pi = pf = pg = po = 0.f;
            }
            pi += lp[hlc]           + sp[hlc];
            pf += lp[Hsz + hlc]     + sp[Hsz + hlc];
            pg += lp[2 * Hsz + hlc] + sp[2 * Hsz + hlc];
            po += lp[3 * Hsz + hlc] + sp[3 * Hsz + hlc];
            float cprev = (s > 0) ? out_c[base - Hsz + hlc] : 0.f;
            float c = sigmoidf_(pf) * cprev + sigmoidf_(pi) * tanhf(pg);
            cv[j] = c;
            hv[j] = sigmoidf_(po) * tanhf(c);
        }
        #pragma unroll
        for (int j = 0; j < 2; j++) {
            *(float4*)(out_h + base + hl0 + j * 4) =
                make_float4(hv[j*4], hv[j*4+1], hv[j*4+2], hv[j*4+3]);
            *(float4*)(out_c + base + hl0 + j * 4) =
                make_float4(cv[j*4], cv[j*4+1], cv[j*4+2], cv[j*4+3]);
        }
        __nv_bfloat162 dh[4], dl[4];
        #pragma unroll
        for (int j = 0; j < 4; j++) {
            float x0 = hv[2*j], x1 = hv[2*j+1];
            __nv_bfloat16 b0 = __float2bfloat16(x0);
            __nv_bfloat16 b1 = __float2bfloat16(x1);
            dh[j] = __nv_bfloat162(b0, b1);
            dl[j] = __nv_bfloat162(__float2bfloat16(x0 - __bfloat162float(b0)),
                                   __float2bfloat16(x1 - __bfloat162float(b1)));
        }
        *(uint4*)(g_h_hi[wbuf] + (size_t)b * Hsz + h0 + hl0) = *(const uint4*)dh;
        *(uint4*)(g_h_lo[wbuf] + (size_t)b * Hsz + h0 + hl0) = *(const uint4*)dl;
    }
}

// ---------------------------------------------------------------------------
extern "C" void kernel_launch(void* const* d_in, const int* in_sizes, int n_in,
                              void* d_out, int out_size) {
    const int*   letter_seq = (const int*)d_in[0];
    const int*   state_seq  = (const int*)d_in[1];
    const float* letter_emb = (const float*)d_in[2];
    const float* state_emb  = (const float*)d_in[3];
    const float* W_ih       = (const float*)d_in[4];
    const float* W_hh       = (const float*)d_in[5];
    const float* b_ih       = (const float*)d_in[6];
    const float* b_hh       = (const float*)d_in[7];

    float* out_h = (float*)d_out;
    float* out_c = out_h + (size_t)Bsz * Ssz * Hsz;

    static int smem_set = 0;
    if (!smem_set) {
        cudaFuncSetAttribute(lstm_step_mma,
                             cudaFuncAttributeMaxDynamicSharedMemorySize,
                             SMEM_TOTAL);
        smem_set = 1;
    }

    wsplit_kernel<<<(G4 * Hsz) / (256 * 4), 256>>>(W_hh);
    proj_kernel<<<dim3(G4 / 8, 34), 256>>>(letter_emb, state_emb, W_ih, b_ih, b_hh);

    for (int s = 0; s < Ssz; s++) {
        lstm_step_mma<<<dim3(Hsz / HT, Bsz / BMt), 256, SMEM_TOTAL>>>(
            letter_seq, state_seq, out_h, out_c, s);
    }
}